// round 13
// baseline (speedup 1.0000x reference)
#include <cuda_runtime.h>
#include <cuda_bf16.h>
#include <math.h>

#define BATCH 1024
#define LSEQ  200
#define HDIM  128
#define MAXN  201
#define NNODE 200000
#define STRIDE 132        // padded fp32 row stride (conflict-free, 16B-aligned)
#define ESTRIDE 12        // s_e row stride: float4-aligned
#define K1_BLOCKS 1024
#define K0_BLOCKS 3125    // 200000 / 64

__device__ __forceinline__ unsigned smem_u32(const void* p) {
    return (unsigned)__cvta_generic_to_shared(p);
}
#define CP_ASYNC16(dst, src) \
    asm volatile("cp.async.cg.shared.global [%0], [%1], 16;\n" :: "r"(dst), "l"(src))
#define CP_COMMIT() asm volatile("cp.async.commit_group;\n" ::: "memory")
#define CP_WAIT0()  asm volatile("cp.async.wait_group 0;\n" ::: "memory")

// ---------------------------------------------------------------------------
// Fused kernel with INTERLEAVED roles: for bid < 4096, bid%4==0 -> a-path
// (batch = bid/4), else b-path; bids 4096..4148 -> b-path tail. Every
// scheduling wave mixes ~1:3 a:b so HBM streaming overlaps a-path stalls.
// ---------------------------------------------------------------------------
__global__ void __launch_bounds__(512, 2) k_all(
    const int* __restrict__ alias_, const int* __restrict__ items,
    const int* __restrict__ mask, const float* __restrict__ emb,
    const float* __restrict__ W0, const float* __restrict__ b0,
    const float* __restrict__ W1, const float* __restrict__ b1,
    const float* __restrict__ W2, const float* __restrict__ b2,
    const float* __restrict__ Wq, const float* __restrict__ bq,
    const float* __restrict__ Wt, const float* __restrict__ bt,
    const float* __restrict__ ln_g, const float* __restrict__ ln_b,
    float* __restrict__ outA, float* __restrict__ outB)
{
    extern __shared__ float sm[];
    int tid = threadIdx.x;
    int w = tid >> 5, lane = tid & 31;
    const float4* emb4 = (const float4*)emb;

    // ---- role remap: interleave a and b blocks within waves ----
    int bid = blockIdx.x;
    int role_a, rid;
    if (bid < 4096) {
        if ((bid & 3) == 0) { role_a = 1; rid = bid >> 2; }
        else                { role_a = 0; rid = bid - (bid >> 2) - 1; }
    } else {
        role_a = 0; rid = 3072 + (bid - 4096);
    }

    // ======================= b-path role =======================
    if (!role_a) {
        int i0 = rid * 64;
        #pragma unroll
        for (int rr = 0; rr < 4; rr++) {
            int il = w * 4 + rr;
            int i = i0 + il;
            float4 v = emb4[(size_t)i * 32 + lane];
            float ss = v.x * v.x + v.y * v.y + v.z * v.z + v.w * v.w;
            #pragma unroll
            for (int o = 16; o; o >>= 1) ss += __shfl_xor_sync(0xffffffffu, ss, o);
            float s = 1.0f / (sqrtf(ss) + 1e-12f);
            *(float4*)&sm[il * STRIDE + lane * 4] =
                make_float4(v.x * s, v.y * s, v.z * s, v.w * s);
        }
        __syncthreads();
        for (int idx = tid; idx < 8192; idx += 512) {
            int c = idx >> 6, il = idx & 63;
            int gi = i0 + il;
            if (gi >= 1)
                __stcs(&outB[(size_t)c * (NNODE - 1) + (gi - 1)],
                       sm[il * STRIDE + c]);
        }
        return;
    }

    // ======================= a-path role =======================
    float* s_tile = sm;                    // 100*132 = 13200
    float* s_V    = sm + 13200;            // 64*132  = 8448
    float* s_e    = sm + 21648;            // 200*12  = 2400
    float* s_rn   = sm + 24048;            // 200
    int*   s_item = (int*)(sm + 24248);    // 200
    float* s_ht   = sm + 24448;            // 128
    float* s_hts  = sm + 24576;            // 128
    float* s_q0   = sm + 24704;            // 128
    float* s_vb   = sm + 24832;            // 64
    float* s_den  = sm + 24896;            // 8
    float* s_T    = sm + 24904;            // 8
    // aliases inside dead V region (pass-A dots finished before use):
    float* s_S    = s_V + 1024;            // 1024
    float* s_cat  = s_V + 2048;            // 256
    float* s_f    = s_V + 2304;            // 128
    __shared__ int s_len;

    int b = rid;

    // ---- items + len (mask is a prefix: find the 1->0 edge) ----
    if (tid < LSEQ) {
        int m  = mask[b * LSEQ + tid];
        int mn = (tid < LSEQ - 1) ? mask[b * LSEQ + tid + 1] : 0;
        if (m && !mn) s_len = tid + 1;
        s_item[tid] = items[b * MAXN + alias_[b * LSEQ + tid]];
    }
    __syncthreads();
    int len = s_len;
    int r0end = (len < 100) ? len : 100;   // rows in round 0
    int r1end = (len > 100) ? (len - 100) : 0;

    // ---- prefetch round-0 rows (raw) into tile; hidden by head chain ----
    for (int r = w; r < r0end; r += 16) {
        const char* src = (const char*)(emb + (size_t)s_item[r] * HDIM)
                          + lane * 16;
        CP_ASYNC16(smem_u32(s_tile + r * STRIDE + lane * 4), src);
    }
    CP_COMMIT();

    // ---- ht = normalized last seq row (warp 0, direct LDG) ----
    if (w == 0) {
        int it = s_item[len - 1];
        float4 v = emb4[(size_t)it * 32 + lane];
        float ss = v.x * v.x + v.y * v.y + v.z * v.z + v.w * v.w;
        #pragma unroll
        for (int o = 16; o; o >>= 1) ss += __shfl_xor_sync(0xffffffffu, ss, o);
        float s = 1.0f / (sqrtf(ss) + 1e-12f);
        *(float4*)&s_ht[lane * 4] =
            make_float4(v.x * s, v.y * s, v.z * s, v.w * s);
    }
    __syncthreads();

    // ---- hts[o] = sign-ish(ht . Wq[o] + bq[o]) ----
    #pragma unroll
    for (int o = w; o < HDIM; o += 16) {
        float4 wv = ((const float4*)(Wq + o * HDIM))[lane];
        float4 xv = ((const float4*)s_ht)[lane];
        float p = wv.x * xv.x + wv.y * xv.y + wv.z * xv.z + wv.w * xv.w;
        #pragma unroll
        for (int off = 16; off; off >>= 1) p += __shfl_xor_sync(0xffffffffu, p, off);
        if (lane == 0) {
            float t = p + bq[o];
            s_hts[o] = t / (fabsf(t) + 1e-12f);
        }
    }
    __syncthreads();

    // ---- q0 = hts @ W0^T + b0 ----
    #pragma unroll
    for (int o = w; o < HDIM; o += 16) {
        float4 wv = ((const float4*)(W0 + o * HDIM))[lane];
        float4 xv = ((const float4*)s_hts)[lane];
        float p = wv.x * xv.x + wv.y * xv.y + wv.z * xv.z + wv.w * xv.w;
        #pragma unroll
        for (int off = 16; off; off >>= 1) p += __shfl_xor_sync(0xffffffffu, p, off);
        if (lane == 0) s_q0[o] = p + b0[o];
    }
    __syncthreads();

    // ---- V[h][j][c] = sum_d q0[h*16+d]*W1[j*16+d, c] ----
    for (int p = tid; p < 1024; p += 512) {       // p = (j, c)
        int j = p >> 7, c = p & 127;
        float w1d[16];
        #pragma unroll
        for (int d = 0; d < 16; d++) w1d[d] = W1[(j * 16 + d) * HDIM + c];
        #pragma unroll
        for (int h = 0; h < 8; h++) {
            float acc = 0.0f;
            #pragma unroll
            for (int d = 0; d < 16; d++) acc += s_q0[h * 16 + d] * w1d[d];
            s_V[(h * 8 + j) * STRIDE + c] = acc;
        }
    }
    if (tid < 64) {
        int h = tid >> 3, j = tid & 7;
        float acc = 0.0f;
        #pragma unroll
        for (int d = 0; d < 16; d++) acc += s_q0[h * 16 + d] * b1[j * 16 + d];
        s_vb[tid] = acc;
    }

    // ================= pass A, round 0 (heads 0-3, rows 0..r0end) =========
    CP_WAIT0();
    __syncthreads();
    // norms of loaded rows (LDS + shuffle)
    for (int r = w; r < r0end; r += 16) {
        float4 v = *(const float4*)&s_tile[r * STRIDE + lane * 4];
        float ss = v.x * v.x + v.y * v.y + v.z * v.z + v.w * v.w;
        #pragma unroll
        for (int o = 16; o; o >>= 1) ss += __shfl_xor_sync(0xffffffffu, ss, o);
        if (lane == 0) s_rn[r] = 1.0f / (sqrtf(ss) + 1e-12f);
    }
    __syncthreads();
    {
        int hh = w >> 2, jp = w & 3;
        int h = hh;                        // heads 0..3
        if (lane < 25) {
            int row = h * 25 + lane;
            float acc0 = 0.f, acc1 = 0.f;
            if (h * 25 < len) {            // head has at least one live row
                const float4* sr = (const float4*)(s_tile + row * STRIDE);
                const float4* v0 = (const float4*)(s_V + (h * 8 + jp * 2) * STRIDE);
                const float4* v1 = (const float4*)(s_V + (h * 8 + jp * 2 + 1) * STRIDE);
                #pragma unroll
                for (int k = 0; k < 32; k++) {
                    float4 x = sr[k], a = v0[k], c = v1[k];
                    acc0 += x.x*a.x + x.y*a.y + x.z*a.z + x.w*a.w;
                    acc1 += x.x*c.x + x.y*c.y + x.z*c.z + x.w*c.w;
                }
            }
            float rnv = s_rn[row];         // garbage if row>=len; select discards
            float x0 = ((row < len) ? acc0 * rnv : 0.0f) + s_vb[h * 8 + jp * 2];
            float x1 = ((row < len) ? acc1 * rnv : 0.0f) + s_vb[h * 8 + jp * 2 + 1];
            int l0 = lane * 8 + jp * 2;
            s_e[l0 * ESTRIDE + h]       = __expf(2.0f / (1.0f + __expf(-x0)));
            s_e[(l0 + 1) * ESTRIDE + h] = __expf(2.0f / (1.0f + __expf(-x1)));
        }
    }
    __syncthreads();                       // dots done before tile overwrite

    // ================= pass A, round 1 (heads 4-7, rows 100..len) =========
    for (int r = w; r < r1end; r += 16) {
        const char* src = (const char*)(emb + (size_t)s_item[100 + r] * HDIM)
                          + lane * 16;
        CP_ASYNC16(smem_u32(s_tile + r * STRIDE + lane * 4), src);
    }
    CP_COMMIT();
    CP_WAIT0();
    __syncthreads();
    for (int r = w; r < r1end; r += 16) {
        float4 v = *(const float4*)&s_tile[r * STRIDE + lane * 4];
        float ss = v.x * v.x + v.y * v.y + v.z * v.z + v.w * v.w;
        #pragma unroll
        for (int o = 16; o; o >>= 1) ss += __shfl_xor_sync(0xffffffffu, ss, o);
        if (lane == 0) s_rn[100 + r] = 1.0f / (sqrtf(ss) + 1e-12f);
    }
    __syncthreads();
    {
        int hh = w >> 2, jp = w & 3;
        int h = 4 + hh;                    // heads 4..7
        if (lane < 25) {
            int row  = h * 25 + lane;      // 100 + hh*25 + lane
            int slot = hh * 25 + lane;
            float acc0 = 0.f, acc1 = 0.f;
            if (h * 25 < len) {
                const float4* sr = (const float4*)(s_tile + slot * STRIDE);
                const float4* v0 = (const float4*)(s_V + (h * 8 + jp * 2) * STRIDE);
                const float4* v1 = (const float4*)(s_V + (h * 8 + jp * 2 + 1) * STRIDE);
                #pragma unroll
                for (int k = 0; k < 32; k++) {
                    float4 x = sr[k], a = v0[k], c = v1[k];
                    acc0 += x.x*a.x + x.y*a.y + x.z*a.z + x.w*a.w;
                    acc1 += x.x*c.x + x.y*c.y + x.z*c.z + x.w*c.w;
                }
            }
            float rnv = s_rn[row];
            float x0 = ((row < len) ? acc0 * rnv : 0.0f) + s_vb[h * 8 + jp * 2];
            float x1 = ((row < len) ? acc1 * rnv : 0.0f) + s_vb[h * 8 + jp * 2 + 1];
            int l0 = lane * 8 + jp * 2;
            s_e[l0 * ESTRIDE + h]       = __expf(2.0f / (1.0f + __expf(-x0)));
            s_e[(l0 + 1) * ESTRIDE + h] = __expf(2.0f / (1.0f + __expf(-x1)));
        }
    }
    __syncthreads();

    // ---- den (warps 0-7, all 200 l) and masked sum T (warps 8-15) ----
    if (w < 8) {
        float p = 0.0f;
        for (int l = lane; l < LSEQ; l += 32) p += s_e[l * ESTRIDE + w];
        #pragma unroll
        for (int off = 16; off; off >>= 1) p += __shfl_xor_sync(0xffffffffu, p, off);
        if (lane == 0) s_den[w] = 1.0f / p;
    } else {
        int hh = w - 8;
        float p = 0.0f;
        for (int l = lane; l < len; l += 32) p += s_e[l * ESTRIDE + hh];
        #pragma unroll
        for (int off = 16; off; off >>= 1) p += __shfl_xor_sync(0xffffffffu, p, off);
        if (lane == 0) s_T[hh] = p;
    }
    __syncthreads();
    if (tid < 8) s_T[tid] *= s_den[tid];
    // fold mask * rn[l] * (1/den[h]) into weights (only l < len used later)
    for (int idx = tid; idx < 1600; idx += 512) {
        int l = idx >> 3, h = idx & 7;
        if (l < len)
            s_e[l * ESTRIDE + h] *= s_den[h] * s_rn[l];
    }
    __syncthreads();

    // ---- pass B: S[h,k] = sum_l em[l,h]*row_l[k]; tile-resident when possible
    {
        int tile_off = (len > 100) ? 100 : 0;  // tile holds rows [tile_off, len)
        int lg = tid >> 6;        // 0..7 l-group
        int k2 = tid & 63;        // float2 column
        const float2* emb2 = (const float2*)emb;
        float ax[8], ay[8];
        #pragma unroll
        for (int h = 0; h < 8; h++) { ax[h] = 0.0f; ay[h] = 0.0f; }
        for (int l = lg; l < len; l += 8) {
            float2 u;
            if (l >= tile_off)
                u = *(const float2*)&s_tile[(l - tile_off) * STRIDE + k2 * 2];
            else
                u = __ldg(&emb2[(size_t)s_item[l] * 64 + k2]);
            float4 e0 = *(const float4*)&s_e[l * ESTRIDE];
            float4 e1 = *(const float4*)&s_e[l * ESTRIDE + 4];
            ax[0] += e0.x * u.x; ay[0] += e0.x * u.y;
            ax[1] += e0.y * u.x; ay[1] += e0.y * u.y;
            ax[2] += e0.z * u.x; ay[2] += e0.z * u.y;
            ax[3] += e0.w * u.x; ay[3] += e0.w * u.y;
            ax[4] += e1.x * u.x; ay[4] += e1.x * u.y;
            ax[5] += e1.y * u.x; ay[5] += e1.y * u.y;
            ax[6] += e1.z * u.x; ay[6] += e1.z * u.y;
            ax[7] += e1.w * u.x; ay[7] += e1.w * u.y;
        }
        float2* pp = (float2*)s_V;   // partials [lg][h][64] in dead V region
        #pragma unroll
        for (int h = 0; h < 8; h++)
            pp[lg * 512 + h * 64 + k2] = make_float2(ax[h], ay[h]);
    }
    __syncthreads();
    {
        int h = tid >> 6, k2 = tid & 63;
        const float2* pp = (const float2*)s_V;
        float sx = 0.0f, sy = 0.0f;
        #pragma unroll
        for (int lg = 0; lg < 8; lg++) {
            float2 q = pp[lg * 512 + h * 64 + k2];
            sx += q.x; sy += q.y;
        }
        ((float2*)s_S)[h * 64 + k2] = make_float2(sx, sy);
    }
    __syncthreads();

    // ---- a[c] = W2[c,:] . S[c/16,:] + b2[c]*T[c/16]  -> s_f ----
    #pragma unroll
    for (int c = w; c < HDIM; c += 16) {
        float4 wv = ((const float4*)(W2 + c * HDIM))[lane];
        float4 sv = *(const float4*)&s_S[(c >> 4) * HDIM + lane * 4];
        float p = wv.x * sv.x + wv.y * sv.y + wv.z * sv.z + wv.w * sv.w;
        #pragma unroll
        for (int off = 16; off; off >>= 1) p += __shfl_xor_sync(0xffffffffu, p, off);
        if (lane == 0) s_f[c] = p + b2[c] * s_T[c >> 4];
    }
    __syncthreads();

    // ---- LayerNorm -> s_cat[0:128]; ht -> s_cat[128:256] ----
    if (w == 0) {
        float4 v = ((const float4*)s_f)[lane];
        float sum = v.x + v.y + v.z + v.w;
        #pragma unroll
        for (int off = 16; off; off >>= 1) sum += __shfl_xor_sync(0xffffffffu, sum, off);
        float mu = sum * (1.0f / 128.0f);
        float dx = v.x - mu, dy = v.y - mu, dz = v.z - mu, dw = v.w - mu;
        float vs = dx * dx + dy * dy + dz * dz + dw * dw;
        #pragma unroll
        for (int off = 16; off; off >>= 1) vs += __shfl_xor_sync(0xffffffffu, vs, off);
        float rstd = rsqrtf(vs * (1.0f / 128.0f) + 1e-8f);
        int c = lane * 4;
        s_cat[c + 0] = dx * rstd * ln_g[c + 0] + ln_b[c + 0];
        s_cat[c + 1] = dy * rstd * ln_g[c + 1] + ln_b[c + 1];
        s_cat[c + 2] = dz * rstd * ln_g[c + 2] + ln_b[c + 2];
        s_cat[c + 3] = dw * rstd * ln_g[c + 3] + ln_b[c + 3];
    }
    if (w == 1) {
        ((float4*)(s_cat + 128))[lane] = ((const float4*)s_ht)[lane];
    }
    __syncthreads();

    // ---- f[o] = Wt[o,:256] . cat + bt[o] ----
    #pragma unroll
    for (int o = w; o < HDIM; o += 16) {
        const float4* wr = (const float4*)(Wt + o * 256);
        float4 x0 = ((const float4*)s_cat)[lane];
        float4 w0v = wr[lane];
        float4 x1 = ((const float4*)s_cat)[lane + 32];
        float4 w1v = wr[lane + 32];
        float p = x0.x * w0v.x + x0.y * w0v.y + x0.z * w0v.z + x0.w * w0v.w
                + x1.x * w1v.x + x1.y * w1v.y + x1.z * w1v.z + x1.w * w1v.w;
        #pragma unroll
        for (int off = 16; off; off >>= 1) p += __shfl_xor_sync(0xffffffffu, p, off);
        if (lane == 0) s_f[o] = p + bt[o];
    }
    __syncthreads();

    // ---- final normalize + write ----
    if (w == 0) {
        float4 v = ((const float4*)s_f)[lane];
        float ss = v.x * v.x + v.y * v.y + v.z * v.z + v.w * v.w;
        #pragma unroll
        for (int off = 16; off; off >>= 1) ss += __shfl_xor_sync(0xffffffffu, ss, off);
        float rn = 1.0f / (sqrtf(ss) + 1e-12f);
        ((float4*)(outA + (size_t)b * HDIM))[lane] =
            make_float4(v.x * rn, v.y * rn, v.z * rn, v.w * rn);
    }
}

// ---------------------------------------------------------------------------
extern "C" void kernel_launch(void* const* d_in, const int* in_sizes, int n_in,
                              void* d_out, int out_size) {
    const int*   alias_ = (const int*)d_in[0];
    const int*   items  = (const int*)d_in[1];
    const int*   mask   = (const int*)d_in[2];
    const float* emb    = (const float*)d_in[3];
    const float* W0     = (const float*)d_in[4];
    const float* b0     = (const float*)d_in[5];
    const float* W1     = (const float*)d_in[6];
    const float* b1     = (const float*)d_in[7];
    const float* W2     = (const float*)d_in[8];
    const float* b2     = (const float*)d_in[9];
    const float* Wq     = (const float*)d_in[10];
    const float* bq     = (const float*)d_in[11];
    const float* Wt     = (const float*)d_in[12];
    const float* bt     = (const float*)d_in[13];
    const float* ln_g   = (const float*)d_in[14];
    const float* ln_b   = (const float*)d_in[15];

    float* out  = (float*)d_out;
    float* outA = out;                    // (1024,128)
    float* outB = out + BATCH * HDIM;     // (128,199999)

    const int smem_bytes = 24912 * (int)sizeof(float);   // 99,648 B
    cudaFuncSetAttribute(k_all,
                         cudaFuncAttributeMaxDynamicSharedMemorySize, smem_bytes);
    k_all<<<K1_BLOCKS + K0_BLOCKS, 512, smem_bytes>>>(
        alias_, items, mask, emb, W0, b0, W1, b1, W2, b2, Wq, bq,
        Wt, bt, ln_g, ln_b, outA, outB);
}

// round 14
// speedup vs baseline: 1.7815x; 1.7815x over previous
#include <cuda_runtime.h>
#include <cuda_bf16.h>
#include <math.h>

#define BATCH 1024
#define LSEQ  200
#define HDIM  128
#define MAXN  201
#define NNODE 200000
#define STRIDE 132        // padded fp32 row stride (conflict-free, 16B-aligned)
#define ESTRIDE 12        // s_e row stride: float4-aligned
#define K1_BLOCKS 1024
#define K0_BLOCKS 3125    // 200000 / 64

__device__ __forceinline__ unsigned smem_u32(const void* p) {
    return (unsigned)__cvta_generic_to_shared(p);
}
#define CP_ASYNC16(dst, src) \
    asm volatile("cp.async.cg.shared.global [%0], [%1], 16;\n" :: "r"(dst), "l"(src))
#define CP_COMMIT() asm volatile("cp.async.commit_group;\n" ::: "memory")
#define CP_WAIT0()  asm volatile("cp.async.wait_group 0;\n" ::: "memory")
#define L2_PREFETCH(p) asm volatile("prefetch.global.L2 [%0];" :: "l"(p))

// ---------------------------------------------------------------------------
// Fused kernel: blocks [0,1024) = a-path (one per batch);
// blocks [1024,4149) = b-path. a-blocks first = LPT scheduling (slow first).
// ---------------------------------------------------------------------------
__global__ void __launch_bounds__(512, 2) k_all(
    const int* __restrict__ alias_, const int* __restrict__ items,
    const int* __restrict__ mask, const float* __restrict__ emb,
    const float* __restrict__ W0, const float* __restrict__ b0,
    const float* __restrict__ W1, const float* __restrict__ b1,
    const float* __restrict__ W2, const float* __restrict__ b2,
    const float* __restrict__ Wq, const float* __restrict__ bq,
    const float* __restrict__ Wt, const float* __restrict__ bt,
    const float* __restrict__ ln_g, const float* __restrict__ ln_b,
    float* __restrict__ outA, float* __restrict__ outB)
{
    extern __shared__ float sm[];
    int tid = threadIdx.x;
    int w = tid >> 5, lane = tid & 31;
    const float4* emb4 = (const float4*)emb;

    // ======================= b-path role =======================
    if (blockIdx.x >= K1_BLOCKS) {
        int i0 = (blockIdx.x - K1_BLOCKS) * 64;
        // batch all 4 row loads first (MLP=4), then reduce/store
        float4 v[4];
        #pragma unroll
        for (int rr = 0; rr < 4; rr++) {
            int i = i0 + w * 4 + rr;
            v[rr] = emb4[(size_t)i * 32 + lane];
        }
        #pragma unroll
        for (int rr = 0; rr < 4; rr++) {
            int il = w * 4 + rr;
            float ss = v[rr].x * v[rr].x + v[rr].y * v[rr].y
                     + v[rr].z * v[rr].z + v[rr].w * v[rr].w;
            #pragma unroll
            for (int o = 16; o; o >>= 1) ss += __shfl_xor_sync(0xffffffffu, ss, o);
            float s = 1.0f / (sqrtf(ss) + 1e-12f);
            *(float4*)&sm[il * STRIDE + lane * 4] =
                make_float4(v[rr].x * s, v[rr].y * s, v[rr].z * s, v[rr].w * s);
        }
        __syncthreads();
        for (int idx = tid; idx < 8192; idx += 512) {
            int c = idx >> 6, il = idx & 63;
            int gi = i0 + il;
            if (gi >= 1)
                __stcs(&outB[(size_t)c * (NNODE - 1) + (gi - 1)],
                       sm[il * STRIDE + c]);
        }
        return;
    }

    // ======================= a-path role =======================
    float* s_tile = sm;                    // 100*132 = 13200
    float* s_V    = sm + 13200;            // 64*132  = 8448
    float* s_e    = sm + 21648;            // 200*12  = 2400
    float* s_rn   = sm + 24048;            // 200
    int*   s_item = (int*)(sm + 24248);    // 200
    float* s_ht   = sm + 24448;            // 128
    float* s_hts  = sm + 24576;            // 128
    float* s_q0   = sm + 24704;            // 128
    float* s_vb   = sm + 24832;            // 64
    float* s_den  = sm + 24896;            // 8
    float* s_T    = sm + 24904;            // 8
    // aliases inside dead V region (pass-A dots finished before use):
    float* s_S    = s_V + 1024;            // 1024
    float* s_cat  = s_V + 2048;            // 256
    float* s_f    = s_V + 2304;            // 128
    __shared__ int s_len;

    int b = blockIdx.x;

    // ---- items + len (mask is a prefix: find the 1->0 edge) ----
    if (tid < LSEQ) {
        int m  = mask[b * LSEQ + tid];
        int mn = (tid < LSEQ - 1) ? mask[b * LSEQ + tid + 1] : 0;
        if (m && !mn) s_len = tid + 1;
        s_item[tid] = items[b * MAXN + alias_[b * LSEQ + tid]];
    }
    __syncthreads();
    int len = s_len;
    int r0end = (len < 100) ? len : 100;   // rows in round 0
    int r1end = (len > 100) ? (len - 100) : 0;

    // ---- prefetch round-0 rows (raw) into tile; hidden by head chain ----
    for (int r = w; r < r0end; r += 16) {
        const char* src = (const char*)(emb + (size_t)s_item[r] * HDIM)
                          + lane * 16;
        CP_ASYNC16(smem_u32(s_tile + r * STRIDE + lane * 4), src);
    }
    CP_COMMIT();

    // ---- L2-prefetch round-1 rows so the later cp.async hits L2 ----
    if (r1end > 0 && lane < 4) {
        for (int r = w; r < r1end; r += 16) {
            const char* p = (const char*)(emb + (size_t)s_item[100 + r] * HDIM);
            L2_PREFETCH(p + lane * 128);
        }
    }

    // ---- ht = normalized last seq row (warp 0, direct LDG) ----
    if (w == 0) {
        int it = s_item[len - 1];
        float4 v = emb4[(size_t)it * 32 + lane];
        float ss = v.x * v.x + v.y * v.y + v.z * v.z + v.w * v.w;
        #pragma unroll
        for (int o = 16; o; o >>= 1) ss += __shfl_xor_sync(0xffffffffu, ss, o);
        float s = 1.0f / (sqrtf(ss) + 1e-12f);
        *(float4*)&s_ht[lane * 4] =
            make_float4(v.x * s, v.y * s, v.z * s, v.w * s);
    }
    __syncthreads();

    // ---- hts[o] = sign-ish(ht . Wq[o] + bq[o]) ----
    #pragma unroll
    for (int o = w; o < HDIM; o += 16) {
        float4 wv = ((const float4*)(Wq + o * HDIM))[lane];
        float4 xv = ((const float4*)s_ht)[lane];
        float p = wv.x * xv.x + wv.y * xv.y + wv.z * xv.z + wv.w * xv.w;
        #pragma unroll
        for (int off = 16; off; off >>= 1) p += __shfl_xor_sync(0xffffffffu, p, off);
        if (lane == 0) {
            float t = p + bq[o];
            s_hts[o] = t / (fabsf(t) + 1e-12f);
        }
    }
    __syncthreads();

    // ---- q0 = hts @ W0^T + b0 ----
    #pragma unroll
    for (int o = w; o < HDIM; o += 16) {
        float4 wv = ((const float4*)(W0 + o * HDIM))[lane];
        float4 xv = ((const float4*)s_hts)[lane];
        float p = wv.x * xv.x + wv.y * xv.y + wv.z * xv.z + wv.w * xv.w;
        #pragma unroll
        for (int off = 16; off; off >>= 1) p += __shfl_xor_sync(0xffffffffu, p, off);
        if (lane == 0) s_q0[o] = p + b0[o];
    }
    __syncthreads();

    // ---- V[h][j][c] = sum_d q0[h*16+d]*W1[j*16+d, c] ----
    for (int p = tid; p < 1024; p += 512) {       // p = (j, c)
        int j = p >> 7, c = p & 127;
        float w1d[16];
        #pragma unroll
        for (int d = 0; d < 16; d++) w1d[d] = W1[(j * 16 + d) * HDIM + c];
        #pragma unroll
        for (int h = 0; h < 8; h++) {
            float acc = 0.0f;
            #pragma unroll
            for (int d = 0; d < 16; d++) acc += s_q0[h * 16 + d] * w1d[d];
            s_V[(h * 8 + j) * STRIDE + c] = acc;
        }
    }
    if (tid < 64) {
        int h = tid >> 3, j = tid & 7;
        float acc = 0.0f;
        #pragma unroll
        for (int d = 0; d < 16; d++) acc += s_q0[h * 16 + d] * b1[j * 16 + d];
        s_vb[tid] = acc;
    }

    // ================= pass A, round 0 (heads 0-3, rows 0..r0end) =========
    CP_WAIT0();
    __syncthreads();
    // norms of loaded rows (LDS + shuffle)
    for (int r = w; r < r0end; r += 16) {
        float4 v = *(const float4*)&s_tile[r * STRIDE + lane * 4];
        float ss = v.x * v.x + v.y * v.y + v.z * v.z + v.w * v.w;
        #pragma unroll
        for (int o = 16; o; o >>= 1) ss += __shfl_xor_sync(0xffffffffu, ss, o);
        if (lane == 0) s_rn[r] = 1.0f / (sqrtf(ss) + 1e-12f);
    }
    __syncthreads();
    {
        int hh = w >> 2, jp = w & 3;
        int h = hh;                        // heads 0..3
        if (lane < 25) {
            int row = h * 25 + lane;
            float acc0 = 0.f, acc1 = 0.f;
            if (h * 25 < len) {            // head has at least one live row
                const float4* sr = (const float4*)(s_tile + row * STRIDE);
                const float4* v0 = (const float4*)(s_V + (h * 8 + jp * 2) * STRIDE);
                const float4* v1 = (const float4*)(s_V + (h * 8 + jp * 2 + 1) * STRIDE);
                #pragma unroll
                for (int k = 0; k < 32; k++) {
                    float4 x = sr[k], a = v0[k], c = v1[k];
                    acc0 += x.x*a.x + x.y*a.y + x.z*a.z + x.w*a.w;
                    acc1 += x.x*c.x + x.y*c.y + x.z*c.z + x.w*c.w;
                }
            }
            float rnv = s_rn[row];         // garbage if row>=len; select discards
            float x0 = ((row < len) ? acc0 * rnv : 0.0f) + s_vb[h * 8 + jp * 2];
            float x1 = ((row < len) ? acc1 * rnv : 0.0f) + s_vb[h * 8 + jp * 2 + 1];
            int l0 = lane * 8 + jp * 2;
            s_e[l0 * ESTRIDE + h]       = __expf(2.0f / (1.0f + __expf(-x0)));
            s_e[(l0 + 1) * ESTRIDE + h] = __expf(2.0f / (1.0f + __expf(-x1)));
        }
    }
    __syncthreads();                       // dots done before tile overwrite

    // ================= pass A, round 1 (heads 4-7, rows 100..len) =========
    for (int r = w; r < r1end; r += 16) {
        const char* src = (const char*)(emb + (size_t)s_item[100 + r] * HDIM)
                          + lane * 16;
        CP_ASYNC16(smem_u32(s_tile + r * STRIDE + lane * 4), src);
    }
    CP_COMMIT();
    CP_WAIT0();
    __syncthreads();
    for (int r = w; r < r1end; r += 16) {
        float4 v = *(const float4*)&s_tile[r * STRIDE + lane * 4];
        float ss = v.x * v.x + v.y * v.y + v.z * v.z + v.w * v.w;
        #pragma unroll
        for (int o = 16; o; o >>= 1) ss += __shfl_xor_sync(0xffffffffu, ss, o);
        if (lane == 0) s_rn[100 + r] = 1.0f / (sqrtf(ss) + 1e-12f);
    }
    __syncthreads();
    {
        int hh = w >> 2, jp = w & 3;
        int h = 4 + hh;                    // heads 4..7
        if (lane < 25) {
            int row  = h * 25 + lane;      // 100 + hh*25 + lane
            int slot = hh * 25 + lane;
            float acc0 = 0.f, acc1 = 0.f;
            if (h * 25 < len) {
                const float4* sr = (const float4*)(s_tile + slot * STRIDE);
                const float4* v0 = (const float4*)(s_V + (h * 8 + jp * 2) * STRIDE);
                const float4* v1 = (const float4*)(s_V + (h * 8 + jp * 2 + 1) * STRIDE);
                #pragma unroll
                for (int k = 0; k < 32; k++) {
                    float4 x = sr[k], a = v0[k], c = v1[k];
                    acc0 += x.x*a.x + x.y*a.y + x.z*a.z + x.w*a.w;
                    acc1 += x.x*c.x + x.y*c.y + x.z*c.z + x.w*c.w;
                }
            }
            float rnv = s_rn[row];
            float x0 = ((row < len) ? acc0 * rnv : 0.0f) + s_vb[h * 8 + jp * 2];
            float x1 = ((row < len) ? acc1 * rnv : 0.0f) + s_vb[h * 8 + jp * 2 + 1];
            int l0 = lane * 8 + jp * 2;
            s_e[l0 * ESTRIDE + h]       = __expf(2.0f / (1.0f + __expf(-x0)));
            s_e[(l0 + 1) * ESTRIDE + h] = __expf(2.0f / (1.0f + __expf(-x1)));
        }
    }
    __syncthreads();

    // ---- den (warps 0-7, all 200 l) and masked sum T (warps 8-15) ----
    if (w < 8) {
        float p = 0.0f;
        for (int l = lane; l < LSEQ; l += 32) p += s_e[l * ESTRIDE + w];
        #pragma unroll
        for (int off = 16; off; off >>= 1) p += __shfl_xor_sync(0xffffffffu, p, off);
        if (lane == 0) s_den[w] = 1.0f / p;
    } else {
        int hh = w - 8;
        float p = 0.0f;
        for (int l = lane; l < len; l += 32) p += s_e[l * ESTRIDE + hh];
        #pragma unroll
        for (int off = 16; off; off >>= 1) p += __shfl_xor_sync(0xffffffffu, p, off);
        if (lane == 0) s_T[hh] = p;
    }
    __syncthreads();
    if (tid < 8) s_T[tid] *= s_den[tid];
    // fold mask * rn[l] * (1/den[h]) into weights (only l < len used later)
    for (int idx = tid; idx < 1600; idx += 512) {
        int l = idx >> 3, h = idx & 7;
        if (l < len)
            s_e[l * ESTRIDE + h] *= s_den[h] * s_rn[l];
    }
    __syncthreads();

    // ---- pass B: S[h,k] = sum_l em[l,h]*row_l[k]; tile-resident when possible
    {
        int tile_off = (len > 100) ? 100 : 0;  // tile holds rows [tile_off, len)
        int lg = tid >> 6;        // 0..7 l-group
        int k2 = tid & 63;        // float2 column
        const float2* emb2 = (const float2*)emb;
        float ax[8], ay[8];
        #pragma unroll
        for (int h = 0; h < 8; h++) { ax[h] = 0.0f; ay[h] = 0.0f; }
        for (int l = lg; l < len; l += 8) {
            float2 u;
            if (l >= tile_off)
                u = *(const float2*)&s_tile[(l - tile_off) * STRIDE + k2 * 2];
            else
                u = __ldg(&emb2[(size_t)s_item[l] * 64 + k2]);
            float4 e0 = *(const float4*)&s_e[l * ESTRIDE];
            float4 e1 = *(const float4*)&s_e[l * ESTRIDE + 4];
            ax[0] += e0.x * u.x; ay[0] += e0.x * u.y;
            ax[1] += e0.y * u.x; ay[1] += e0.y * u.y;
            ax[2] += e0.z * u.x; ay[2] += e0.z * u.y;
            ax[3] += e0.w * u.x; ay[3] += e0.w * u.y;
            ax[4] += e1.x * u.x; ay[4] += e1.x * u.y;
            ax[5] += e1.y * u.x; ay[5] += e1.y * u.y;
            ax[6] += e1.z * u.x; ay[6] += e1.z * u.y;
            ax[7] += e1.w * u.x; ay[7] += e1.w * u.y;
        }
        float2* pp = (float2*)s_V;   // partials [lg][h][64] in dead V region
        #pragma unroll
        for (int h = 0; h < 8; h++)
            pp[lg * 512 + h * 64 + k2] = make_float2(ax[h], ay[h]);
    }
    __syncthreads();
    {
        int h = tid >> 6, k2 = tid & 63;
        const float2* pp = (const float2*)s_V;
        float sx = 0.0f, sy = 0.0f;
        #pragma unroll
        for (int lg = 0; lg < 8; lg++) {
            float2 q = pp[lg * 512 + h * 64 + k2];
            sx += q.x; sy += q.y;
        }
        ((float2*)s_S)[h * 64 + k2] = make_float2(sx, sy);
    }
    __syncthreads();

    // ---- a[c] = W2[c,:] . S[c/16,:] + b2[c]*T[c/16]  -> s_f ----
    #pragma unroll
    for (int c = w; c < HDIM; c += 16) {
        float4 wv = ((const float4*)(W2 + c * HDIM))[lane];
        float4 sv = *(const float4*)&s_S[(c >> 4) * HDIM + lane * 4];
        float p = wv.x * sv.x + wv.y * sv.y + wv.z * sv.z + wv.w * sv.w;
        #pragma unroll
        for (int off = 16; off; off >>= 1) p += __shfl_xor_sync(0xffffffffu, p, off);
        if (lane == 0) s_f[c] = p + b2[c] * s_T[c >> 4];
    }
    __syncthreads();

    // ---- LayerNorm -> s_cat[0:128]; ht -> s_cat[128:256] ----
    if (w == 0) {
        float4 v = ((const float4*)s_f)[lane];
        float sum = v.x + v.y + v.z + v.w;
        #pragma unroll
        for (int off = 16; off; off >>= 1) sum += __shfl_xor_sync(0xffffffffu, sum, off);
        float mu = sum * (1.0f / 128.0f);
        float dx = v.x - mu, dy = v.y - mu, dz = v.z - mu, dw = v.w - mu;
        float vs = dx * dx + dy * dy + dz * dz + dw * dw;
        #pragma unroll
        for (int off = 16; off; off >>= 1) vs += __shfl_xor_sync(0xffffffffu, vs, off);
        float rstd = rsqrtf(vs * (1.0f / 128.0f) + 1e-8f);
        int c = lane * 4;
        s_cat[c + 0] = dx * rstd * ln_g[c + 0] + ln_b[c + 0];
        s_cat[c + 1] = dy * rstd * ln_g[c + 1] + ln_b[c + 1];
        s_cat[c + 2] = dz * rstd * ln_g[c + 2] + ln_b[c + 2];
        s_cat[c + 3] = dw * rstd * ln_g[c + 3] + ln_b[c + 3];
    }
    if (w == 1) {
        ((float4*)(s_cat + 128))[lane] = ((const float4*)s_ht)[lane];
    }
    __syncthreads();

    // ---- f[o] = Wt[o,:256] . cat + bt[o] ----
    #pragma unroll
    for (int o = w; o < HDIM; o += 16) {
        const float4* wr = (const float4*)(Wt + o * 256);
        float4 x0 = ((const float4*)s_cat)[lane];
        float4 w0v = wr[lane];
        float4 x1 = ((const float4*)s_cat)[lane + 32];
        float4 w1v = wr[lane + 32];
        float p = x0.x * w0v.x + x0.y * w0v.y + x0.z * w0v.z + x0.w * w0v.w
                + x1.x * w1v.x + x1.y * w1v.y + x1.z * w1v.z + x1.w * w1v.w;
        #pragma unroll
        for (int off = 16; off; off >>= 1) p += __shfl_xor_sync(0xffffffffu, p, off);
        if (lane == 0) s_f[o] = p + bt[o];
    }
    __syncthreads();

    // ---- final normalize + write ----
    if (w == 0) {
        float4 v = ((const float4*)s_f)[lane];
        float ss = v.x * v.x + v.y * v.y + v.z * v.z + v.w * v.w;
        #pragma unroll
        for (int off = 16; off; off >>= 1) ss += __shfl_xor_sync(0xffffffffu, ss, off);
        float rn = 1.0f / (sqrtf(ss) + 1e-12f);
        ((float4*)(outA + (size_t)b * HDIM))[lane] =
            make_float4(v.x * rn, v.y * rn, v.z * rn, v.w * rn);
    }
}

// ---------------------------------------------------------------------------
extern "C" void kernel_launch(void* const* d_in, const int* in_sizes, int n_in,
                              void* d_out, int out_size) {
    const int*   alias_ = (const int*)d_in[0];
    const int*   items  = (const int*)d_in[1];
    const int*   mask   = (const int*)d_in[2];
    const float* emb    = (const float*)d_in[3];
    const float* W0     = (const float*)d_in[4];
    const float* b0     = (const float*)d_in[5];
    const float* W1     = (const float*)d_in[6];
    const float* b1     = (const float*)d_in[7];
    const float* W2     = (const float*)d_in[8];
    const float* b2     = (const float*)d_in[9];
    const float* Wq     = (const float*)d_in[10];
    const float* bq     = (const float*)d_in[11];
    const float* Wt     = (const float*)d_in[12];
    const float* bt     = (const float*)d_in[13];
    const float* ln_g   = (const float*)d_in[14];
    const float* ln_b   = (const float*)d_in[15];

    float* out  = (float*)d_out;
    float* outA = out;                    // (1024,128)
    float* outB = out + BATCH * HDIM;     // (128,199999)

    const int smem_bytes = 24912 * (int)sizeof(float);   // 99,648 B
    cudaFuncSetAttribute(k_all,
                         cudaFuncAttributeMaxDynamicSharedMemorySize, smem_bytes);
    k_all<<<K1_BLOCKS + K0_BLOCKS, 512, smem_bytes>>>(
        alias_, items, mask, emb, W0, b0, W1, b1, W2, b2, Wq, bq,
        Wt, bt, ln_g, ln_b, outA, outB);
}